// round 1
// baseline (speedup 1.0000x reference)
#include <cuda_runtime.h>
#include <cstdint>

// RealNVP: 15 coupling layers, each with two MLPs 1->32->16->1 (leaky_relu 0.01),
// log_scale = tanh(mlp_s(x1))*sw + sb ; z2' = exp(log_scale)*x2 + mlp_t(x1)
// Output layout assumed: [ concat(z1,z2) (N,2) row-major | ld (N,1) ]  -> 3N floats.
//
// Strategy: 2 points per thread packed into f32x2 registers; all MLP math via
// fma.rn.f32x2 (2x fp32 throughput on sm_103a). Weights duplicated (w,w) in
// shared memory so each broadcast LDS.128 feeds two FFMA2s.

#define NLAYERS 15
#define LAYER_STRIDE 1222               // packed 8B units per layer
#define SMEM_UNITS (NLAYERS * LAYER_STRIDE)
#define SMEM_BYTES (SMEM_UNITS * 8)     // 146,640 B

__device__ __forceinline__ uint64_t pk2(float a, float b) {
    uint64_t r; asm("mov.b64 %0, {%1, %2};" : "=l"(r) : "f"(a), "f"(b)); return r;
}
__device__ __forceinline__ void up2(uint64_t v, float& a, float& b) {
    asm("mov.b64 {%0, %1}, %2;" : "=f"(a), "=f"(b) : "l"(v));
}
__device__ __forceinline__ uint64_t fma2(uint64_t a, uint64_t b, uint64_t c) {
    uint64_t d; asm("fma.rn.f32x2 %0, %1, %2, %3;" : "=l"(d) : "l"(a), "l"(b), "l"(c)); return d;
}
__device__ __forceinline__ uint64_t mul2(uint64_t a, uint64_t b) {
    uint64_t d; asm("mul.rn.f32x2 %0, %1, %2;" : "=l"(d) : "l"(a), "l"(b)); return d;
}
__device__ __forceinline__ uint64_t add2(uint64_t a, uint64_t b) {
    uint64_t d; asm("add.rn.f32x2 %0, %1, %2;" : "=l"(d) : "l"(a), "l"(b)); return d;
}

// leaky_relu(h, 0.01) == 0.505*h + 0.495*|h|   (branch-free, packed)
__device__ __forceinline__ uint64_t lrelu2(uint64_t h) {
    uint64_t a = h & 0x7FFFFFFF7FFFFFFFULL;
    uint64_t m = mul2(h, pk2(0.505f, 0.505f));
    return fma2(a, pk2(0.495f, 0.495f), m);
}

// Per-layer per-MLP SMEM layout (packed 8B units, all 16B-aligned sub-arrays):
//   [0,64)    interleaved (W1[i], b1[i]) pairs       (32 x 16B)
//   [64,576)  W2 rows: i-major, 16 packed per row    (32 x 8 x 16B)
//   [576,592) b2
//   [592,608) W3
//   [608]     b3, [609] pad
// MLP t at +610; sw at [1220], sb at [1221].
__device__ __forceinline__ uint64_t mlp2(uint64_t x1, const unsigned long long* __restrict__ p) {
    uint64_t h2[16];
    const ulonglong2* b2v = reinterpret_cast<const ulonglong2*>(p + 576);
#pragma unroll
    for (int jj = 0; jj < 8; jj++) {
        ulonglong2 b = b2v[jj];
        h2[2 * jj] = b.x; h2[2 * jj + 1] = b.y;
    }
    const ulonglong2* w1b1 = reinterpret_cast<const ulonglong2*>(p);
    const ulonglong2* W2   = reinterpret_cast<const ulonglong2*>(p + 64);
#pragma unroll 4
    for (int i = 0; i < 32; i++) {
        ulonglong2 wb = w1b1[i];
        uint64_t h1 = lrelu2(fma2(x1, wb.x, wb.y));
        const ulonglong2* row = W2 + i * 8;
#pragma unroll
        for (int jj = 0; jj < 8; jj++) {
            ulonglong2 w = row[jj];
            h2[2 * jj]     = fma2(h1, w.x, h2[2 * jj]);
            h2[2 * jj + 1] = fma2(h1, w.y, h2[2 * jj + 1]);
        }
    }
    const ulonglong2* w3v = reinterpret_cast<const ulonglong2*>(p + 592);
    uint64_t out = p[608];
#pragma unroll
    for (int jj = 0; jj < 8; jj++) {
        ulonglong2 w = w3v[jj];
        out = fma2(lrelu2(h2[2 * jj]),     w.x, out);
        out = fma2(lrelu2(h2[2 * jj + 1]), w.y, out);
    }
    return out;
}

extern __shared__ unsigned long long smw[];

__global__ __launch_bounds__(512, 1) void realnvp_kernel(
    const float* __restrict__ x,
    const float* __restrict__ scale_w, const float* __restrict__ scale_b,
    const float* __restrict__ sW1, const float* __restrict__ sb1,
    const float* __restrict__ sW2, const float* __restrict__ sb2,
    const float* __restrict__ sW3, const float* __restrict__ sb3,
    const float* __restrict__ tW1, const float* __restrict__ tb1,
    const float* __restrict__ tW2, const float* __restrict__ tb2,
    const float* __restrict__ tW3, const float* __restrict__ tb3,
    float* __restrict__ out, int npairs)
{
    // Stage duplicated weights into shared memory.
    for (int idx = threadIdx.x; idx < SMEM_UNITS; idx += blockDim.x) {
        int l = idx / LAYER_STRIDE;
        int k = idx - l * LAYER_STRIDE;
        float v = 0.0f;
        if (k >= 1220) {
            v = (k == 1220) ? scale_w[l] : scale_b[l];
        } else {
            const float *W1 = sW1, *b1 = sb1, *W2 = sW2, *b2 = sb2, *W3 = sW3, *b3 = sb3;
            int kk = k;
            if (k >= 610) { kk = k - 610; W1 = tW1; b1 = tb1; W2 = tW2; b2 = tb2; W3 = tW3; b3 = tb3; }
            if (kk < 64)        v = (kk & 1) ? b1[l * 32 + (kk >> 1)] : W1[l * 32 + (kk >> 1)];
            else if (kk < 576)  v = W2[l * 512 + (kk - 64)];
            else if (kk < 592)  v = b2[l * 16 + (kk - 576)];
            else if (kk < 608)  v = W3[l * 16 + (kk - 592)];
            else if (kk == 608) v = b3[l];
            else                v = 0.0f;   // pad
        }
        smw[idx] = pk2(v, v);
    }
    __syncthreads();

    const int stride = gridDim.x * blockDim.x;
    for (int p = blockIdx.x * blockDim.x + threadIdx.x; p < npairs; p += stride) {
        float4 xv = *reinterpret_cast<const float4*>(x + 4 * (size_t)p);
        uint64_t z1 = pk2(xv.y, xv.w);   // x[:,1] for points 2p, 2p+1
        uint64_t z2 = pk2(xv.x, xv.z);   // x[:,0]
        uint64_t ld = 0;                 // (0.f, 0.f)

#pragma unroll 1
        for (int l = 0; l < NLAYERS; l++) {
            const unsigned long long* base = smw + l * LAYER_STRIDE;
            uint64_t x1 = z2;
            uint64_t x2 = z1;

            uint64_t s = mlp2(x1, base);
            float a, b; up2(s, a, b);
            uint64_t th   = pk2(tanhf(a), tanhf(b));
            uint64_t logs = fma2(th, base[1220], base[1221]);

            uint64_t t = mlp2(x1, base + 610);

            up2(logs, a, b);
            uint64_t ex  = pk2(__expf(a), __expf(b));
            uint64_t z2n = fma2(ex, x2, t);

            ld = add2(ld, logs);
            z1 = x1;
            z2 = z2n;
        }

        float z1a, z1b, z2a, z2b, la, lb;
        up2(z1, z1a, z1b); up2(z2, z2a, z2b); up2(ld, la, lb);
        float4 o; o.x = z1a; o.y = z2a; o.z = z1b; o.w = z2b;
        *reinterpret_cast<float4*>(out + 4 * (size_t)p) = o;
        float2 lo2; lo2.x = la; lo2.y = lb;
        *reinterpret_cast<float2*>(out + 4 * (size_t)npairs + 2 * (size_t)p) = lo2;
    }
}

extern "C" void kernel_launch(void* const* d_in, const int* in_sizes, int n_in,
                              void* d_out, int out_size) {
    const float* x       = (const float*)d_in[0];
    const float* scale_w = (const float*)d_in[1];
    const float* scale_b = (const float*)d_in[2];
    const float* sW1 = (const float*)d_in[3];
    const float* sb1 = (const float*)d_in[4];
    const float* sW2 = (const float*)d_in[5];
    const float* sb2 = (const float*)d_in[6];
    const float* sW3 = (const float*)d_in[7];
    const float* sb3 = (const float*)d_in[8];
    const float* tW1 = (const float*)d_in[9];
    const float* tb1 = (const float*)d_in[10];
    const float* tW2 = (const float*)d_in[11];
    const float* tb2 = (const float*)d_in[12];
    const float* tW3 = (const float*)d_in[13];
    const float* tb3 = (const float*)d_in[14];
    float* out = (float*)d_out;

    int npairs = in_sizes[0] / 4;   // x has N*2 floats; 2 points per thread

    cudaFuncSetAttribute(realnvp_kernel, cudaFuncAttributeMaxDynamicSharedMemorySize, SMEM_BYTES);
    realnvp_kernel<<<148, 512, SMEM_BYTES>>>(
        x, scale_w, scale_b, sW1, sb1, sW2, sb2, sW3, sb3,
        tW1, tb1, tW2, tb2, tW3, tb3, out, npairs);
}